// round 11
// baseline (speedup 1.0000x reference)
#include <cuda_runtime.h>
#include <cuda_fp16.h>
#include <math.h>
#include <stdint.h>

// ---------------- problem constants -----------------------------------------
#define TOKENS 4096
#define DDIM   1024
#define FDIM   4096
#define NEXP   8
#define PAIRS  (TOKENS * 2)
#define CAP    TOKENS

// ---------------- GEMM tiling ------------------------------------------------
#define BM 128
#define BN 256
#define BK 32
#define NTH 256                    // 8 warps, 2(m) x 4(n), warp tile 64x64
#define NSTAGE 4
#define A_BYTES  (BM * 80)         // 10240 (LDT=40 halves, 80B rows)
#define B_BYTES  (BN * 80)         // 20480
#define STAGE_BYTES (A_BYTES + B_BYTES)            // 30720
#define SOFF_STAGE 1024
#define SMEM_BYTES (SOFF_STAGE + NSTAGE * STAGE_BYTES)  // 123904

// ---------------- scratch (136 MB — R2-proven budget) ----------------------------
__device__ int    g_counts[NEXP];
__device__ int    g_list[NEXP * CAP];
__device__ float  g_prob[PAIRS];
__device__ __half g_xf[(size_t)TOKENS * DDIM];          // fp16 x   (8 MB)
__device__ __half g_hf[(size_t)PAIRS * FDIM];           // fp16 h   (64 MB)
__device__ __half g_wf[(size_t)NEXP * FDIM * DDIM];     // fp16 W   (64 MB, reused)

// ---------------- ptx helpers --------------------------------------------------
__device__ __forceinline__ uint32_t smem_u32(const void* p) {
    uint32_t a;
    asm("{ .reg .u64 t; cvta.to.shared.u64 t, %1; cvt.u32.u64 %0, t; }"
        : "=r"(a) : "l"(p));
    return a;
}
__device__ __forceinline__ void cp16(uint32_t dst, const void* src) {
    asm volatile("cp.async.cg.shared.global [%0], [%1], 16;" :: "r"(dst), "l"(src));
}
__device__ __forceinline__ void cp_commit() {
    asm volatile("cp.async.commit_group;" ::: "memory");
}
template <int N>
__device__ __forceinline__ void cp_wait() {
    asm volatile("cp.async.wait_group %0;" :: "n"(N) : "memory");
}
__device__ __forceinline__ void ldm4(uint32_t* r, uint32_t a) {
    asm volatile("ldmatrix.sync.aligned.m8n8.x4.shared.b16 {%0,%1,%2,%3}, [%4];"
                 : "=r"(r[0]), "=r"(r[1]), "=r"(r[2]), "=r"(r[3]) : "r"(a));
}
__device__ __forceinline__ void mma_f16(float* c, const uint32_t* a, const uint32_t* b) {
    asm volatile(
        "mma.sync.aligned.m16n8k16.row.col.f32.f16.f16.f32 "
        "{%0,%1,%2,%3}, {%4,%5,%6,%7}, {%8,%9}, {%0,%1,%2,%3};"
        : "+f"(c[0]), "+f"(c[1]), "+f"(c[2]), "+f"(c[3])
        : "r"(a[0]), "r"(a[1]), "r"(a[2]), "r"(a[3]), "r"(b[0]), "r"(b[1]));
}

// ---------------- math helpers --------------------------------------------------
__device__ __forceinline__ float gelu_tanh(float v) {
    const float c = 0.7978845608028654f;
    float u = c * (v + 0.044715f * v * v * v);
    return 0.5f * v * (1.0f + tanhf(u));
}

// ---------------- kernel 0: zero output + counts --------------------------------
__global__ void zero_kernel(float* __restrict__ out, int n) {
    int i = blockIdx.x * blockDim.x + threadIdx.x;
    if (i < n) out[i] = 0.0f;
    if (blockIdx.x == 0 && threadIdx.x < NEXP) g_counts[threadIdx.x] = 0;
}

// ---------------- prepass: W fp32 [f][e][k] -> fp16 [e][f][k] --------------------
__global__ void conv_w_kernel(const float4* __restrict__ w, int OUTER, int KD) {
    size_t n4 = (size_t)OUTER * NEXP * (KD >> 2);
    size_t stride = (size_t)gridDim.x * blockDim.x;
    for (size_t i = blockIdx.x * (size_t)blockDim.x + threadIdx.x; i < n4; i += stride) {
        int kd4 = KD >> 2;
        size_t fe = i / kd4;
        int k4 = (int)(i - fe * kd4);
        int f = (int)(fe / NEXP);
        int e = (int)(fe - (size_t)f * NEXP);
        float4 v = w[i];
        __half2 h0 = __halves2half2(__float2half_rn(v.x), __float2half_rn(v.y));
        __half2 h1 = __halves2half2(__float2half_rn(v.z), __float2half_rn(v.w));
        size_t o = ((size_t)e * OUTER + f) * KD + (size_t)k4 * 4;
        *reinterpret_cast<uint2*>(g_wf + o) =
            make_uint2(*(uint32_t*)&h0, *(uint32_t*)&h1);
    }
}

// ---------------- kernel: gate + x->fp16 convert (fused) -------------------------
__global__ __launch_bounds__(256) void gate_kernel(
    const float* __restrict__ x, const float* __restrict__ gw)
{
    int t = blockIdx.x;
    const float* xr = x + (size_t)t * DDIM;

    float acc[NEXP];
#pragma unroll
    for (int e = 0; e < NEXP; e++) acc[e] = 0.0f;
    for (int d = threadIdx.x; d < DDIM; d += 256) {
        float xv = xr[d];
        g_xf[(size_t)t * DDIM + d] = __float2half_rn(xv);
#pragma unroll
        for (int e = 0; e < NEXP; e++) acc[e] += xv * gw[e * DDIM + d];
    }
#pragma unroll
    for (int e = 0; e < NEXP; e++) {
#pragma unroll
        for (int o = 16; o > 0; o >>= 1)
            acc[e] += __shfl_xor_sync(0xffffffff, acc[e], o);
    }
    __shared__ float red[NEXP][8];
    int warp = threadIdx.x >> 5, lane = threadIdx.x & 31;
    if (lane == 0) {
#pragma unroll
        for (int e = 0; e < NEXP; e++) red[e][warp] = acc[e];
    }
    __syncthreads();
    if (threadIdx.x == 0) {
        float lg[NEXP];
#pragma unroll
        for (int e = 0; e < NEXP; e++) {
            float s = 0.0f;
#pragma unroll
            for (int w = 0; w < 8; w++) s += red[e][w];
            lg[e] = s;
        }
        float mx = lg[0];
#pragma unroll
        for (int e = 1; e < NEXP; e++) mx = fmaxf(mx, lg[e]);
        float pe[NEXP], s = 0.0f;
#pragma unroll
        for (int e = 0; e < NEXP; e++) { pe[e] = expf(lg[e] - mx); s += pe[e]; }
        float inv = 1.0f / s;
        int i0 = 0;
#pragma unroll
        for (int e = 1; e < NEXP; e++) if (pe[e] > pe[i0]) i0 = e;
        int i1 = (i0 == 0) ? 1 : 0;
#pragma unroll
        for (int e = 0; e < NEXP; e++)
            if (e != i0 && pe[e] > pe[i1]) i1 = e;
        int p0 = t * 2, p1 = t * 2 + 1;
        g_prob[p0] = pe[i0] * inv;
        g_prob[p1] = pe[i1] * inv;
        int pos0 = atomicAdd(&g_counts[i0], 1);
        g_list[i0 * CAP + pos0] = p0;
        int pos1 = atomicAdd(&g_counts[i1], 1);
        g_list[i1 * CAP + pos1] = p1;
    }
}

// ---------------- grouped fp16 GEMM: 64x64 warp tiles, 4-stage pipeline ----------
// C[m,n] = sum_k A[row(m),k] * Wf[e][n0+n][k]; KSPLIT=2 on layer 2.
template <int KDIM, int NOUT, bool L2TAG>
__global__ __launch_bounds__(NTH, 1)
void moe_fp16(const float* __restrict__ bias,
              float* __restrict__ dout)
{
    constexpr int KSPLIT = L2TAG ? 2 : 1;
    constexpr int KLOC = KDIM / KSPLIT;
    constexpr int NCH = KLOC / BK;          // 32 (L1) / 64 (L2)

    int e   = blockIdx.z;
    int cnt = g_counts[e];
    int m0  = blockIdx.y * BM;
    if (m0 >= cnt) return;
    int ks    = blockIdx.x % KSPLIT;
    int n0    = (blockIdx.x / KSPLIT) * BN;
    int kbase = ks * KLOC;

    extern __shared__ __align__(128) char smem[];
    uint32_t sb = smem_u32(smem);
    int* rows = (int*)smem;

    int tid = threadIdx.x, wid = tid >> 5, lane = tid & 31;

    if (tid < BM) {
        int m = m0 + tid;
        rows[tid] = g_list[e * CAP + (m < cnt ? m : m0)];
    }
    __syncthreads();

    // ---- cp.async mappings ----
    // A: 2 threads/row, 32B each (128 rows x 64B)
    int ar = tid >> 1;
    int ao = (tid & 1) * 32;
    int pa = rows[ar];
    const __half* a_rowp = L2TAG ? (g_hf + (size_t)pa * KDIM)
                                 : (g_xf + (size_t)(pa >> 1) * KDIM);
    const char* a_src = (const char*)(a_rowp + kbase) + ao;
    uint32_t a_dst = sb + SOFF_STAGE + (uint32_t)ar * 80 + ao;
    // B: 1 thread/row, 64B (256 rows)
    const char* b_src = (const char*)(g_wf + ((size_t)e * NOUT + n0 + tid) * KDIM + kbase);
    uint32_t b_dst = sb + SOFF_STAGE + A_BYTES + (uint32_t)tid * 80;

    // ---- fragment addressing: 2x4 warps, warp tile 64x64 (R7-validated) ----
    int wm = wid & 1, wn = wid >> 1;
    int li = lane >> 3, lr = lane & 7;
    uint32_t aoff = (uint32_t)((wm * 64 + lr + (li & 1) * 8) * 80 + (li >> 1) * 16);
    uint32_t boff = (uint32_t)((wn * 64 + (li >> 1) * 8 + lr) * 80 + (li & 1) * 16);

    float acc[4][8][4];
#pragma unroll
    for (int im = 0; im < 4; im++)
#pragma unroll
        for (int in = 0; in < 8; in++)
#pragma unroll
            for (int q = 0; q < 4; q++) acc[im][in][q] = 0.0f;

    // ---- prologue: issue stages 0..2 ----
#pragma unroll
    for (int s = 0; s < 3; s++) {
        uint32_t off = (uint32_t)s * STAGE_BYTES;
        int kb = s * BK * 2;
        cp16(a_dst + off, a_src + kb);
        cp16(a_dst + off + 16, a_src + kb + 16);
#pragma unroll
        for (int j = 0; j < 4; j++)
            cp16(b_dst + off + j * 16, b_src + kb + j * 16);
        cp_commit();
    }

    for (int i = 0; i < NCH; i++) {
        cp_wait<2>();          // stage i has landed
        __syncthreads();       // all warps done reading stage i-1's buffer slot

        // issue stage i+3 into buffer (i+3)%4 (just vacated)
        if (i + 3 < NCH) {
            uint32_t off = (uint32_t)((i + 3) & 3) * STAGE_BYTES;
            int kb = (i + 3) * BK * 2;
            cp16(a_dst + off, a_src + kb);
            cp16(a_dst + off + 16, a_src + kb + 16);
#pragma unroll
            for (int j = 0; j < 4; j++)
                cp16(b_dst + off + j * 16, b_src + kb + j * 16);
        }
        cp_commit();

        // compute chunk i: 2 k16 groups, A frags double-buffered
        uint32_t As = sb + SOFF_STAGE + (uint32_t)(i & 3) * STAGE_BYTES;
        uint32_t Bs = As + A_BYTES;
        uint32_t af[2][4];
        ldm4(af[0], As + aoff);
#pragma unroll
        for (int g = 0; g < 2; g++) {
            uint32_t bf[8][2];
#pragma unroll
            for (int h = 0; h < 4; h++) {
                uint32_t t4[4];
                ldm4(t4, Bs + boff + h * 1280 + g * 32);
                bf[2 * h][0] = t4[0]; bf[2 * h][1] = t4[1];
                bf[2 * h + 1][0] = t4[2]; bf[2 * h + 1][1] = t4[3];
            }
#pragma unroll
            for (int im = 0; im < 4; im++) {
                int cb = im & 1;
                if (im < 3)
                    ldm4(af[cb ^ 1], As + aoff + (im + 1) * 1280 + g * 32);
                else if (g == 0)
                    ldm4(af[cb ^ 1], As + aoff + 32);   // A(k16#1, im=0)
#pragma unroll
                for (int in = 0; in < 8; in++)
                    mma_f16(acc[im][in], af[cb], bf[in]);
            }
        }
    }

    // ---- epilogue (R7-validated mapping) ----
    int qr = lane >> 2, qc = (lane & 3) * 2;
#pragma unroll
    for (int im = 0; im < 4; im++) {
#pragma unroll
        for (int half = 0; half < 2; half++) {
            int m_loc = wm * 64 + im * 16 + qr + half * 8;
            if (m0 + m_loc >= cnt) continue;
            int p = rows[m_loc];
            if (!L2TAG) {
                __half* hp = g_hf + (size_t)p * FDIM;
                const float* bb = bias + (size_t)e * FDIM;
#pragma unroll
                for (int in = 0; in < 8; in++) {
                    int col = n0 + wn * 64 + in * 8 + qc;
                    float v0 = acc[im][in][half * 2 + 0] + bb[col];
                    float v1 = acc[im][in][half * 2 + 1] + bb[col + 1];
                    __half2 hv = __halves2half2(__float2half_rn(gelu_tanh(v0)),
                                                __float2half_rn(gelu_tanh(v1)));
                    *reinterpret_cast<uint32_t*>(hp + col) = *(uint32_t*)&hv;
                }
            } else {
                float pr = g_prob[p];
                float* op = dout + (size_t)(p >> 1) * DDIM;
                const float* bb = bias + (size_t)e * DDIM;
#pragma unroll
                for (int in = 0; in < 8; in++) {
                    int col = n0 + wn * 64 + in * 8 + qc;
                    float b0 = (ks == 0) ? bb[col] : 0.0f;
                    float b1 = (ks == 0) ? bb[col + 1] : 0.0f;
                    atomicAdd(&op[col],
                              pr * (acc[im][in][half * 2 + 0] + b0));
                    atomicAdd(&op[col + 1],
                              pr * (acc[im][in][half * 2 + 1] + b1));
                }
            }
        }
    }
}

// ---------------- launch --------------------------------------------------------------
extern "C" void kernel_launch(void* const* d_in, const int* in_sizes, int n_in,
                              void* d_out, int out_size)
{
    (void)in_sizes; (void)n_in; (void)out_size;
    const float* x  = (const float*)d_in[0];
    const float* gw = (const float*)d_in[1];
    const float* w1 = (const float*)d_in[2];
    const float* b1 = (const float*)d_in[3];
    const float* w2 = (const float*)d_in[4];
    const float* b2 = (const float*)d_in[5];
    float* out = (float*)d_out;

    cudaFuncSetAttribute(moe_fp16<DDIM, FDIM, false>,
                         cudaFuncAttributeMaxDynamicSharedMemorySize, SMEM_BYTES);
    cudaFuncSetAttribute(moe_fp16<FDIM, DDIM, true>,
                         cudaFuncAttributeMaxDynamicSharedMemorySize, SMEM_BYTES);

    zero_kernel<<<(TOKENS * DDIM + 255) / 256, 256>>>(out, TOKENS * DDIM);
    gate_kernel<<<TOKENS, 256>>>(x, gw);

    // layer 1: convert w1 -> g_wf, then GEMM
    conv_w_kernel<<<2048, 256>>>((const float4*)w1, FDIM, DDIM);
    dim3 g1(FDIM / BN, TOKENS / BM, NEXP);        // 16 x 32 x 8
    moe_fp16<DDIM, FDIM, false><<<g1, NTH, SMEM_BYTES>>>(b1, nullptr);

    // layer 2: convert w2 -> g_wf (reuse buffer), then GEMM (k-split x2)
    conv_w_kernel<<<2048, 256>>>((const float4*)w2, DDIM, FDIM);
    dim3 g2((DDIM / BN) * 2, TOKENS / BM, NEXP);  // 8 x 32 x 8
    moe_fp16<FDIM, DDIM, true><<<g2, NTH, SMEM_BYTES>>>(b2, out);
}

// round 13
// speedup vs baseline: 1.1340x; 1.1340x over previous
#include <cuda_runtime.h>
#include <cuda_fp16.h>
#include <math.h>
#include <stdint.h>

// ---------------- problem constants -----------------------------------------
#define TOKENS 4096
#define DDIM   1024
#define FDIM   4096
#define NEXP   8
#define PAIRS  (TOKENS * 2)
#define CAP    TOKENS

// ---------------- GEMM tiling ------------------------------------------------
#define BM 128
#define BN 128
#define BK 32
#define NTH 256                    // 8 warps, 2(m) x 4(n), warp tile 64x32
#define NSTAGE 3
#define A_BYTES  (BM * 80)         // 10240 (LDT=40 halves, 80B rows)
#define B_BYTES  (BN * 80)         // 10240
#define STAGE_BYTES (A_BYTES + B_BYTES)                 // 20480
#define SOFF_STAGE 1024
#define SMEM_BYTES (SOFF_STAGE + NSTAGE * STAGE_BYTES)  // 62464

// ---------------- scratch (136 MB — R2-proven budget) ----------------------------
__device__ int    g_counts[NEXP];
__device__ int    g_list[NEXP * CAP];
__device__ float  g_prob[PAIRS];
__device__ __half g_xf[(size_t)TOKENS * DDIM];          // fp16 x   (8 MB)
__device__ __half g_hf[(size_t)PAIRS * FDIM];           // fp16 h   (64 MB)
__device__ __half g_wf[(size_t)NEXP * FDIM * DDIM];     // fp16 W   (64 MB, reused)

// ---------------- ptx helpers --------------------------------------------------
__device__ __forceinline__ uint32_t smem_u32(const void* p) {
    uint32_t a;
    asm("{ .reg .u64 t; cvta.to.shared.u64 t, %1; cvt.u32.u64 %0, t; }"
        : "=r"(a) : "l"(p));
    return a;
}
__device__ __forceinline__ void cp16(uint32_t dst, const void* src) {
    asm volatile("cp.async.cg.shared.global [%0], [%1], 16;" :: "r"(dst), "l"(src));
}
__device__ __forceinline__ void cp_commit() {
    asm volatile("cp.async.commit_group;" ::: "memory");
}
template <int N>
__device__ __forceinline__ void cp_wait() {
    asm volatile("cp.async.wait_group %0;" :: "n"(N) : "memory");
}
__device__ __forceinline__ void ldm4(uint32_t* r, uint32_t a) {
    asm volatile("ldmatrix.sync.aligned.m8n8.x4.shared.b16 {%0,%1,%2,%3}, [%4];"
                 : "=r"(r[0]), "=r"(r[1]), "=r"(r[2]), "=r"(r[3]) : "r"(a));
}
__device__ __forceinline__ void mma_f16(float* c, const uint32_t* a, const uint32_t* b) {
    asm volatile(
        "mma.sync.aligned.m16n8k16.row.col.f32.f16.f16.f32 "
        "{%0,%1,%2,%3}, {%4,%5,%6,%7}, {%8,%9}, {%0,%1,%2,%3};"
        : "+f"(c[0]), "+f"(c[1]), "+f"(c[2]), "+f"(c[3])
        : "r"(a[0]), "r"(a[1]), "r"(a[2]), "r"(a[3]), "r"(b[0]), "r"(b[1]));
}

// ---------------- math helpers --------------------------------------------------
__device__ __forceinline__ float gelu_tanh(float v) {
    const float c = 0.7978845608028654f;
    float u = c * (v + 0.044715f * v * v * v);
    return 0.5f * v * (1.0f + tanhf(u));
}

// ---------------- kernel 0: zero output + counts --------------------------------
__global__ void zero_kernel(float* __restrict__ out, int n) {
    int i = blockIdx.x * blockDim.x + threadIdx.x;
    if (i < n) out[i] = 0.0f;
    if (blockIdx.x == 0 && threadIdx.x < NEXP) g_counts[threadIdx.x] = 0;
}

// ---------------- prepass: W fp32 [f][e][k] -> fp16 [e][f][k] --------------------
__global__ void conv_w_kernel(const float4* __restrict__ w, int OUTER, int KD) {
    size_t n4 = (size_t)OUTER * NEXP * (KD >> 2);
    size_t stride = (size_t)gridDim.x * blockDim.x;
    for (size_t i = blockIdx.x * (size_t)blockDim.x + threadIdx.x; i < n4; i += stride) {
        int kd4 = KD >> 2;
        size_t fe = i / kd4;
        int k4 = (int)(i - fe * kd4);
        int f = (int)(fe / NEXP);
        int e = (int)(fe - (size_t)f * NEXP);
        float4 v = w[i];
        __half2 h0 = __halves2half2(__float2half_rn(v.x), __float2half_rn(v.y));
        __half2 h1 = __halves2half2(__float2half_rn(v.z), __float2half_rn(v.w));
        size_t o = ((size_t)e * OUTER + f) * KD + (size_t)k4 * 4;
        *reinterpret_cast<uint2*>(g_wf + o) =
            make_uint2(*(uint32_t*)&h0, *(uint32_t*)&h1);
    }
}

// ---------------- kernel: gate + x->fp16 convert (fused) -------------------------
__global__ __launch_bounds__(256) void gate_kernel(
    const float* __restrict__ x, const float* __restrict__ gw)
{
    int t = blockIdx.x;
    const float* xr = x + (size_t)t * DDIM;

    float acc[NEXP];
#pragma unroll
    for (int e = 0; e < NEXP; e++) acc[e] = 0.0f;
    for (int d = threadIdx.x; d < DDIM; d += 256) {
        float xv = xr[d];
        g_xf[(size_t)t * DDIM + d] = __float2half_rn(xv);
#pragma unroll
        for (int e = 0; e < NEXP; e++) acc[e] += xv * gw[e * DDIM + d];
    }
#pragma unroll
    for (int e = 0; e < NEXP; e++) {
#pragma unroll
        for (int o = 16; o > 0; o >>= 1)
            acc[e] += __shfl_xor_sync(0xffffffff, acc[e], o);
    }
    __shared__ float red[NEXP][8];
    int warp = threadIdx.x >> 5, lane = threadIdx.x & 31;
    if (lane == 0) {
#pragma unroll
        for (int e = 0; e < NEXP; e++) red[e][warp] = acc[e];
    }
    __syncthreads();
    if (threadIdx.x == 0) {
        float lg[NEXP];
#pragma unroll
        for (int e = 0; e < NEXP; e++) {
            float s = 0.0f;
#pragma unroll
            for (int w = 0; w < 8; w++) s += red[e][w];
            lg[e] = s;
        }
        float mx = lg[0];
#pragma unroll
        for (int e = 1; e < NEXP; e++) mx = fmaxf(mx, lg[e]);
        float pe[NEXP], s = 0.0f;
#pragma unroll
        for (int e = 0; e < NEXP; e++) { pe[e] = expf(lg[e] - mx); s += pe[e]; }
        float inv = 1.0f / s;
        int i0 = 0;
#pragma unroll
        for (int e = 1; e < NEXP; e++) if (pe[e] > pe[i0]) i0 = e;
        int i1 = (i0 == 0) ? 1 : 0;
#pragma unroll
        for (int e = 0; e < NEXP; e++)
            if (e != i0 && pe[e] > pe[i1]) i1 = e;
        int p0 = t * 2, p1 = t * 2 + 1;
        g_prob[p0] = pe[i0] * inv;
        g_prob[p1] = pe[i1] * inv;
        int pos0 = atomicAdd(&g_counts[i0], 1);
        g_list[i0 * CAP + pos0] = p0;
        int pos1 = atomicAdd(&g_counts[i1], 1);
        g_list[i1 * CAP + pos1] = p1;
    }
}

// ---------------- grouped fp16 GEMM: R8 shape, all-cp.async, 3-stage wait<1> -----
// C[m,n] = sum_k A[row(m),k] * Wf[e][n0+n][k]; KSPLIT=2 on layer 2.
template <int KDIM, int NOUT, bool L2TAG>
__global__ __launch_bounds__(NTH, 2)
void moe_fp16(const float* __restrict__ bias,
              float* __restrict__ dout)
{
    constexpr int KSPLIT = L2TAG ? 2 : 1;
    constexpr int KLOC = KDIM / KSPLIT;
    constexpr int NCH = KLOC / BK;

    int e   = blockIdx.z;
    int cnt = g_counts[e];
    int m0  = blockIdx.y * BM;
    if (m0 >= cnt) return;
    int ks    = blockIdx.x % KSPLIT;
    int n0    = (blockIdx.x / KSPLIT) * BN;
    int kbase = ks * KLOC;

    extern __shared__ __align__(128) char smem[];
    uint32_t sb = smem_u32(smem);
    int* rows = (int*)smem;

    int tid = threadIdx.x, wid = tid >> 5, lane = tid & 31;

    if (tid < BM) {
        int m = m0 + tid;
        rows[tid] = g_list[e * CAP + (m < cnt ? m : m0)];
    }
    __syncthreads();

    // ---- cp.async mappings: 2 threads/row, 32B (2 x 16B) each, for A and B ----
    int r  = tid >> 1;
    int ro = (tid & 1) * 32;
    int pa = rows[r];
    const __half* a_rowp = L2TAG ? (g_hf + (size_t)pa * KDIM)
                                 : (g_xf + (size_t)(pa >> 1) * KDIM);
    const char* a_src = (const char*)(a_rowp + kbase) + ro;
    const char* b_src = (const char*)(g_wf + ((size_t)e * NOUT + n0 + r) * KDIM + kbase) + ro;
    uint32_t a_dst = sb + SOFF_STAGE + (uint32_t)r * 80 + ro;
    uint32_t b_dst = a_dst + A_BYTES;

    // ---- fragment addressing (validated R2/R5/R6/R8; LDT=40) ----
    int wm = wid & 1, wn = wid >> 1;
    int li = lane >> 3, lr = lane & 7;
    uint32_t aoff = (uint32_t)((wm * 64 + lr + (li & 1) * 8) * 80 + (li >> 1) * 16);
    uint32_t boff = (uint32_t)((wn * 32 + (li >> 1) * 8 + lr) * 80 + (li & 1) * 16);

    float acc[4][4][4];
#pragma unroll
    for (int im = 0; im < 4; im++)
#pragma unroll
        for (int in = 0; in < 4; in++)
#pragma unroll
            for (int q = 0; q < 4; q++) acc[im][in][q] = 0.0f;

    // ---- prologue: issue stages 0,1 (full 32B per thread per operand) ----
#pragma unroll
    for (int s = 0; s < 2; s++) {
        uint32_t off = (uint32_t)s * STAGE_BYTES;
        int kb = s * BK * 2;
        cp16(a_dst + off,      a_src + kb);
        cp16(a_dst + off + 16, a_src + kb + 16);
        cp16(b_dst + off,      b_src + kb);
        cp16(b_dst + off + 16, b_src + kb + 16);
        cp_commit();
    }

    int stage = 0;
    for (int i = 0; i < NCH; i++) {
        cp_wait<1>();          // stage i landed (stage i+1 may still fly)
        __syncthreads();       // everyone done reading the buffer we're about to refill

        // issue stage i+2 into the slot vacated by stage i-1
        if (i + 2 < NCH) {
            int s2 = stage + 2; if (s2 >= NSTAGE) s2 -= NSTAGE;
            uint32_t off = (uint32_t)s2 * STAGE_BYTES;
            int kb = (i + 2) * BK * 2;
            cp16(a_dst + off,      a_src + kb);
            cp16(a_dst + off + 16, a_src + kb + 16);
            cp16(b_dst + off,      b_src + kb);
            cp16(b_dst + off + 16, b_src + kb + 16);
        }
        cp_commit();

        // compute chunk i (2 k16 groups), B frags double-buffered (R8 style)
        uint32_t As = sb + SOFF_STAGE + (uint32_t)stage * STAGE_BYTES;
        uint32_t Bs = As + A_BYTES;
        uint32_t bf[2][4][2];
        {
            uint32_t t4[4];
            ldm4(t4, Bs + boff);
            bf[0][0][0] = t4[0]; bf[0][0][1] = t4[1];
            bf[0][1][0] = t4[2]; bf[0][1][1] = t4[3];
            ldm4(t4, Bs + boff + 1280);
            bf[0][2][0] = t4[0]; bf[0][2][1] = t4[1];
            bf[0][3][0] = t4[2]; bf[0][3][1] = t4[3];
        }
#pragma unroll
        for (int kk = 0; kk < BK; kk += 16) {
            int cur = (kk >> 4) & 1;
            if (kk + 16 < BK) {
                uint32_t t4[4];
                ldm4(t4, Bs + boff + (kk + 16) * 2);
                bf[cur ^ 1][0][0] = t4[0]; bf[cur ^ 1][0][1] = t4[1];
                bf[cur ^ 1][1][0] = t4[2]; bf[cur ^ 1][1][1] = t4[3];
                ldm4(t4, Bs + boff + 1280 + (kk + 16) * 2);
                bf[cur ^ 1][2][0] = t4[0]; bf[cur ^ 1][2][1] = t4[1];
                bf[cur ^ 1][3][0] = t4[2]; bf[cur ^ 1][3][1] = t4[3];
            }
#pragma unroll
            for (int im = 0; im < 4; im++) {
                uint32_t af[4];
                ldm4(af, As + aoff + im * 1280 + kk * 2);
#pragma unroll
                for (int in = 0; in < 4; in++)
                    mma_f16(acc[im][in], af, bf[cur][in]);
            }
        }
        if (++stage == NSTAGE) stage = 0;
    }

    // ---- epilogue ----
    int qr = lane >> 2, qc = (lane & 3) * 2;
#pragma unroll
    for (int im = 0; im < 4; im++) {
#pragma unroll
        for (int half = 0; half < 2; half++) {
            int m_loc = wm * 64 + im * 16 + qr + half * 8;
            if (m0 + m_loc >= cnt) continue;
            int p = rows[m_loc];
            if (!L2TAG) {
                __half* hp = g_hf + (size_t)p * FDIM;
                const float* bb = bias + (size_t)e * FDIM;
#pragma unroll
                for (int in = 0; in < 4; in++) {
                    int col = n0 + wn * 32 + in * 8 + qc;
                    float v0 = acc[im][in][half * 2 + 0] + bb[col];
                    float v1 = acc[im][in][half * 2 + 1] + bb[col + 1];
                    __half2 hv = __halves2half2(__float2half_rn(gelu_tanh(v0)),
                                                __float2half_rn(gelu_tanh(v1)));
                    *reinterpret_cast<uint32_t*>(hp + col) = *(uint32_t*)&hv;
                }
            } else {
                float pr = g_prob[p];
                float* op = dout + (size_t)(p >> 1) * DDIM;
                const float* bb = bias + (size_t)e * DDIM;
#pragma unroll
                for (int in = 0; in < 4; in++) {
                    int col = n0 + wn * 32 + in * 8 + qc;
                    float b0 = (ks == 0) ? bb[col] : 0.0f;
                    float b1 = (ks == 0) ? bb[col + 1] : 0.0f;
                    atomicAdd(&op[col],
                              pr * (acc[im][in][half * 2 + 0] + b0));
                    atomicAdd(&op[col + 1],
                              pr * (acc[im][in][half * 2 + 1] + b1));
                }
            }
        }
    }
}

// ---------------- launch --------------------------------------------------------------
extern "C" void kernel_launch(void* const* d_in, const int* in_sizes, int n_in,
                              void* d_out, int out_size)
{
    (void)in_sizes; (void)n_in; (void)out_size;
    const float* x  = (const float*)d_in[0];
    const float* gw = (const float*)d_in[1];
    const float* w1 = (const float*)d_in[2];
    const float* b1 = (const float*)d_in[3];
    const float* w2 = (const float*)d_in[4];
    const float* b2 = (const float*)d_in[5];
    float* out = (float*)d_out;

    cudaFuncSetAttribute(moe_fp16<DDIM, FDIM, false>,
                         cudaFuncAttributeMaxDynamicSharedMemorySize, SMEM_BYTES);
    cudaFuncSetAttribute(moe_fp16<FDIM, DDIM, true>,
                         cudaFuncAttributeMaxDynamicSharedMemorySize, SMEM_BYTES);

    zero_kernel<<<(TOKENS * DDIM + 255) / 256, 256>>>(out, TOKENS * DDIM);
    gate_kernel<<<TOKENS, 256>>>(x, gw);

    // layer 1: convert w1 -> g_wf, then GEMM
    conv_w_kernel<<<2048, 256>>>((const float4*)w1, FDIM, DDIM);
    dim3 g1(FDIM / BN, TOKENS / BM, NEXP);        // 32 x 32 x 8
    moe_fp16<DDIM, FDIM, false><<<g1, NTH, SMEM_BYTES>>>(b1, nullptr);

    // layer 2: convert w2 -> g_wf (reuse buffer), then GEMM (k-split x2)
    conv_w_kernel<<<2048, 256>>>((const float4*)w2, DDIM, FDIM);
    dim3 g2((DDIM / BN) * 2, TOKENS / BM, NEXP);  // 16 x 32 x 8
    moe_fp16<FDIM, DDIM, true><<<g2, NTH, SMEM_BYTES>>>(b2, out);
}

// round 15
// speedup vs baseline: 1.2600x; 1.1111x over previous
#include <cuda_runtime.h>
#include <cuda_fp16.h>
#include <math.h>
#include <stdint.h>

// ---------------- problem constants -----------------------------------------
#define TOKENS 4096
#define DDIM   1024
#define FDIM   4096
#define NEXP   8
#define PAIRS  (TOKENS * 2)
#define CAP    TOKENS

// ---------------- GEMM tiling ------------------------------------------------
#define BM 128
#define BN 128
#define BK 32
#define NTH 256                    // 8 warps, 2(m) x 4(n), warp tile 64x32
#define A_BYTES  (BM * 80)         // 10240 (LDT=40 halves, 80B rows)
#define B_BYTES  (BN * 80)         // 10240
#define SOFF_STAGE 1024
#define SOFF_B (SOFF_STAGE + 3 * A_BYTES)
#define SMEM_BYTES (SOFF_STAGE + 3 * A_BYTES + 3 * B_BYTES)   // 62464

// ---------------- scratch (72 MB — proven budget) -------------------------------
__device__ int    g_counts[NEXP];
__device__ int    g_list[NEXP * CAP];
__device__ float  g_prob[PAIRS];
__device__ __half g_xf[(size_t)TOKENS * DDIM];   // fp16 x  (8 MB)
__device__ __half g_hf[(size_t)PAIRS * FDIM];    // fp16 h  (64 MB)

// ---------------- ptx helpers --------------------------------------------------
__device__ __forceinline__ uint32_t smem_u32(const void* p) {
    uint32_t a;
    asm("{ .reg .u64 t; cvta.to.shared.u64 t, %1; cvt.u32.u64 %0, t; }"
        : "=r"(a) : "l"(p));
    return a;
}
__device__ __forceinline__ void cp16(uint32_t dst, const void* src) {
    asm volatile("cp.async.cg.shared.global [%0], [%1], 16;" :: "r"(dst), "l"(src));
}
__device__ __forceinline__ void cp_commit() {
    asm volatile("cp.async.commit_group;" ::: "memory");
}
template <int N>
__device__ __forceinline__ void cp_wait() {
    asm volatile("cp.async.wait_group %0;" :: "n"(N) : "memory");
}
__device__ __forceinline__ void ldm4(uint32_t* r, uint32_t a) {
    asm volatile("ldmatrix.sync.aligned.m8n8.x4.shared.b16 {%0,%1,%2,%3}, [%4];"
                 : "=r"(r[0]), "=r"(r[1]), "=r"(r[2]), "=r"(r[3]) : "r"(a));
}
__device__ __forceinline__ void mma_f16(float* c, const uint32_t* a, const uint32_t* b) {
    asm volatile(
        "mma.sync.aligned.m16n8k16.row.col.f32.f16.f16.f32 "
        "{%0,%1,%2,%3}, {%4,%5,%6,%7}, {%8,%9}, {%0,%1,%2,%3};"
        : "+f"(c[0]), "+f"(c[1]), "+f"(c[2]), "+f"(c[3])
        : "r"(a[0]), "r"(a[1]), "r"(a[2]), "r"(a[3]), "r"(b[0]), "r"(b[1]));
}

// ---------------- math helpers --------------------------------------------------
__device__ __forceinline__ float gelu_tanh(float v) {
    const float c = 0.7978845608028654f;
    float u = c * (v + 0.044715f * v * v * v);
    return 0.5f * v * (1.0f + tanhf(u));
}
__device__ __forceinline__ void conv_sts(char* smem, uint32_t off, float4 v) {
    __half2 h0 = __halves2half2(__float2half_rn(v.x), __float2half_rn(v.y));
    __half2 h1 = __halves2half2(__float2half_rn(v.z), __float2half_rn(v.w));
    *reinterpret_cast<uint2*>(smem + off) =
        make_uint2(*(uint32_t*)&h0, *(uint32_t*)&h1);
}

// ---------------- kernel 0: zero output + counts --------------------------------
__global__ void zero_kernel(float* __restrict__ out, int n) {
    int i = blockIdx.x * blockDim.x + threadIdx.x;
    if (i < n) out[i] = 0.0f;
    if (blockIdx.x == 0 && threadIdx.x < NEXP) g_counts[threadIdx.x] = 0;
}

// ---------------- kernel: gate + x->fp16 convert (fused) -------------------------
__global__ __launch_bounds__(256) void gate_kernel(
    const float* __restrict__ x, const float* __restrict__ gw)
{
    int t = blockIdx.x;
    const float* xr = x + (size_t)t * DDIM;

    float acc[NEXP];
#pragma unroll
    for (int e = 0; e < NEXP; e++) acc[e] = 0.0f;
    for (int d = threadIdx.x; d < DDIM; d += 256) {
        float xv = xr[d];
        g_xf[(size_t)t * DDIM + d] = __float2half_rn(xv);
#pragma unroll
        for (int e = 0; e < NEXP; e++) acc[e] += xv * gw[e * DDIM + d];
    }
#pragma unroll
    for (int e = 0; e < NEXP; e++) {
#pragma unroll
        for (int o = 16; o > 0; o >>= 1)
            acc[e] += __shfl_xor_sync(0xffffffff, acc[e], o);
    }
    __shared__ float red[NEXP][8];
    int warp = threadIdx.x >> 5, lane = threadIdx.x & 31;
    if (lane == 0) {
#pragma unroll
        for (int e = 0; e < NEXP; e++) red[e][warp] = acc[e];
    }
    __syncthreads();
    if (threadIdx.x == 0) {
        float lg[NEXP];
#pragma unroll
        for (int e = 0; e < NEXP; e++) {
            float s = 0.0f;
#pragma unroll
            for (int w = 0; w < 8; w++) s += red[e][w];
            lg[e] = s;
        }
        float mx = lg[0];
#pragma unroll
        for (int e = 1; e < NEXP; e++) mx = fmaxf(mx, lg[e]);
        float pe[NEXP], s = 0.0f;
#pragma unroll
        for (int e = 0; e < NEXP; e++) { pe[e] = expf(lg[e] - mx); s += pe[e]; }
        float inv = 1.0f / s;
        int i0 = 0;
#pragma unroll
        for (int e = 1; e < NEXP; e++) if (pe[e] > pe[i0]) i0 = e;
        int i1 = (i0 == 0) ? 1 : 0;
#pragma unroll
        for (int e = 0; e < NEXP; e++)
            if (e != i0 && pe[e] > pe[i1]) i1 = e;
        int p0 = t * 2, p1 = t * 2 + 1;
        g_prob[p0] = pe[i0] * inv;
        g_prob[p1] = pe[i1] * inv;
        int pos0 = atomicAdd(&g_counts[i0], 1);
        g_list[i0 * CAP + pos0] = p0;
        int pos1 = atomicAdd(&g_counts[i1], 1);
        g_list[i1 * CAP + pos1] = p1;
    }
}

// ---------------- grouped fp16 GEMM (R8 + W-stage hidden in compute) -------------
// Triple-buffered A (cp.async, 2 ahead, wait<1>) and B (LDG->cvt->STS inside
// compute of the previous chunk). One barrier per chunk. KSPLIT=2 on layer 2.
template <int KDIM, bool L2TAG>
__global__ __launch_bounds__(NTH, 2)
void moe_fp16(const float* __restrict__ W,
              const float* __restrict__ bias,
              float* __restrict__ dout)
{
    constexpr int KSPLIT = L2TAG ? 2 : 1;
    constexpr int KLOC = KDIM / KSPLIT;
    constexpr int NCH = KLOC / BK;

    int e   = blockIdx.z;
    int cnt = g_counts[e];
    int m0  = blockIdx.y * BM;
    if (m0 >= cnt) return;
    int ks    = blockIdx.x % KSPLIT;
    int n0    = (blockIdx.x / KSPLIT) * BN;
    int kbase = ks * KLOC;

    extern __shared__ __align__(128) char smem[];
    uint32_t sb = smem_u32(smem);
    int* rows = (int*)smem;

    int tid = threadIdx.x, wid = tid >> 5, lane = tid & 31;

    if (tid < BM) {
        int m = m0 + tid;
        rows[tid] = g_list[e * CAP + (m < cnt ? m : m0)];
    }
    __syncthreads();

    // ---- A: cp.async mapping (2 threads/row, 32B each) ----
    int arow = tid >> 1;
    int pa = rows[arow];
    const __half* a_rowp = L2TAG ? (g_hf + (size_t)pa * KDIM)
                                 : (g_xf + (size_t)(pa >> 1) * KDIM);
    const char* a_src = (const char*)(a_rowp + kbase) + (tid & 1) * 32;
    uint32_t a_dst = sb + SOFF_STAGE + (uint32_t)arow * 80 + (tid & 1) * 32;

    // ---- W: LDG float4 mapping (4 per thread) + STS offsets ----
    const float* wp[4];
    uint32_t woff[4];
#pragma unroll
    for (int j = 0; j < 4; j++) {
        int s = tid + j * 256;
        int r = s >> 3;
        int k4 = (s & 7) << 2;
        wp[j] = W + ((size_t)(n0 + r) * NEXP + e) * KDIM + kbase + k4;
        woff[j] = (uint32_t)r * 80 + (uint32_t)k4 * 2;
    }

    // ---- fragment addressing (validated R2/R5/R6/R8; LDT=40) ----
    int wm = wid & 1, wn = wid >> 1;
    int li = lane >> 3, lr = lane & 7;
    uint32_t aoff = (uint32_t)((wm * 64 + lr + (li & 1) * 8) * 80 + (li >> 1) * 16);
    uint32_t boff = (uint32_t)((wn * 32 + (li >> 1) * 8 + lr) * 80 + (li & 1) * 16);

    float acc[4][4][4];
#pragma unroll
    for (int im = 0; im < 4; im++)
#pragma unroll
        for (int in = 0; in < 4; in++)
#pragma unroll
            for (int q = 0; q < 4; q++) acc[im][in][q] = 0.0f;

    // ---- prologue ----
    // A(0), A(1) in flight (separate groups)
    cp16(a_dst, a_src);
    cp16(a_dst + 16, a_src + 16);
    cp_commit();
    cp16(a_dst + A_BYTES, a_src + BK * 2);
    cp16(a_dst + A_BYTES + 16, a_src + BK * 2 + 16);
    cp_commit();
    // W(0): LDG + cvt + STS into B0 (single exposed-latency stall, once)
    float4 wreg[4];
#pragma unroll
    for (int j = 0; j < 4; j++) wreg[j] = *(const float4*)(wp[j]);
    char* b0c = smem + SOFF_B;
#pragma unroll
    for (int j = 0; j < 4; j++) conv_sts(b0c, woff[j], wreg[j]);
    // W(1) LDG in flight
#pragma unroll
    for (int j = 0; j < 4; j++) wreg[j] = *(const float4*)(wp[j] + BK);

    int sA = 0, sB = 0;        // both track i % 3
    for (int i = 0; i < NCH; i++) {
        cp_wait<1>();          // A(i) landed; A(i+1) may still fly
        __syncthreads();       // compute(i-1) fully done -> buffers reusable

        // issue A(i+2) into buffer (i+2)%3 (last read in compute(i-1))
        if (i + 2 < NCH) {
            int s2 = sA + 2; if (s2 >= 3) s2 -= 3;
            uint32_t off = (uint32_t)s2 * A_BYTES;
            int kb = (i + 2) * BK * 2;
            cp16(a_dst + off, a_src + kb);
            cp16(a_dst + off + 16, a_src + kb + 16);
        }
        cp_commit();

        uint32_t As = sb + SOFF_STAGE + (uint32_t)sA * A_BYTES;
        uint32_t Bs = sb + SOFF_B + (uint32_t)sB * B_BYTES;

        // preload B(k16#0) frags
        uint32_t bf[2][4][2];
        {
            uint32_t t4[4];
            ldm4(t4, Bs + boff);
            bf[0][0][0] = t4[0]; bf[0][0][1] = t4[1];
            bf[0][1][0] = t4[2]; bf[0][1][1] = t4[3];
            ldm4(t4, Bs + boff + 1280);
            bf[0][2][0] = t4[0]; bf[0][2][1] = t4[1];
            bf[0][3][0] = t4[2]; bf[0][3][1] = t4[3];
        }

        // hidden W stage: STS W(i+1) into B((i+1)%3); then LDG W(i+2)
        if (i + 1 < NCH) {
            int s1 = sB + 1; if (s1 >= 3) s1 -= 3;
            char* bc = smem + SOFF_B + (size_t)s1 * B_BYTES;
#pragma unroll
            for (int j = 0; j < 4; j++) conv_sts(bc, woff[j], wreg[j]);
        }
        if (i + 2 < NCH) {
            int k0 = (i + 2) * BK;
#pragma unroll
            for (int j = 0; j < 4; j++) wreg[j] = *(const float4*)(wp[j] + k0);
        }

        // compute chunk i (2 k16 groups), B frags double-buffered
#pragma unroll
        for (int kk = 0; kk < BK; kk += 16) {
            int cur = (kk >> 4) & 1;
            if (kk + 16 < BK) {
                uint32_t t4[4];
                ldm4(t4, Bs + boff + (kk + 16) * 2);
                bf[cur ^ 1][0][0] = t4[0]; bf[cur ^ 1][0][1] = t4[1];
                bf[cur ^ 1][1][0] = t4[2]; bf[cur ^ 1][1][1] = t4[3];
                ldm4(t4, Bs + boff + 1280 + (kk + 16) * 2);
                bf[cur ^ 1][2][0] = t4[0]; bf[cur ^ 1][2][1] = t4[1];
                bf[cur ^ 1][3][0] = t4[2]; bf[cur ^ 1][3][1] = t4[3];
            }
#pragma unroll
            for (int im = 0; im < 4; im++) {
                uint32_t af[4];
                ldm4(af, As + aoff + im * 1280 + kk * 2);
#pragma unroll
                for (int in = 0; in < 4; in++)
                    mma_f16(acc[im][in], af, bf[cur][in]);
            }
        }
        if (++sA == 3) sA = 0;
        if (++sB == 3) sB = 0;
    }

    // ---- epilogue ----
    int qr = lane >> 2, qc = (lane & 3) * 2;
#pragma unroll
    for (int im = 0; im < 4; im++) {
#pragma unroll
        for (int half = 0; half < 2; half++) {
            int m_loc = wm * 64 + im * 16 + qr + half * 8;
            if (m0 + m_loc >= cnt) continue;
            int p = rows[m_loc];
            if (!L2TAG) {
                __half* hp = g_hf + (size_t)p * FDIM;
                const float* bb = bias + (size_t)e * FDIM;
#pragma unroll
                for (int in = 0; in < 4; in++) {
                    int col = n0 + wn * 32 + in * 8 + qc;
                    float v0 = acc[im][in][half * 2 + 0] + bb[col];
                    float v1 = acc[im][in][half * 2 + 1] + bb[col + 1];
                    __half2 hv = __halves2half2(__float2half_rn(gelu_tanh(v0)),
                                                __float2half_rn(gelu_tanh(v1)));
                    *reinterpret_cast<uint32_t*>(hp + col) = *(uint32_t*)&hv;
                }
            } else {
                float pr = g_prob[p];
                float* op = dout + (size_t)(p >> 1) * DDIM;
                const float* bb = bias + (size_t)e * DDIM;
#pragma unroll
                for (int in = 0; in < 4; in++) {
                    int col = n0 + wn * 32 + in * 8 + qc;
                    float b0 = (ks == 0) ? bb[col] : 0.0f;
                    float b1 = (ks == 0) ? bb[col + 1] : 0.0f;
                    atomicAdd(&op[col],
                              pr * (acc[im][in][half * 2 + 0] + b0));
                    atomicAdd(&op[col + 1],
                              pr * (acc[im][in][half * 2 + 1] + b1));
                }
            }
        }
    }
}

// ---------------- launch --------------------------------------------------------------
extern "C" void kernel_launch(void* const* d_in, const int* in_sizes, int n_in,
                              void* d_out, int out_size)
{
    (void)in_sizes; (void)n_in; (void)out_size;
    const float* x  = (const float*)d_in[0];
    const float* gw = (const float*)d_in[1];
    const float* w1 = (const float*)d_in[2];
    const float* b1 = (const float*)d_in[3];
    const float* w2 = (const float*)d_in[4];
    const float* b2 = (const float*)d_in[5];
    float* out = (float*)d_out;

    cudaFuncSetAttribute(moe_fp16<DDIM, false>,
                         cudaFuncAttributeMaxDynamicSharedMemorySize, SMEM_BYTES);
    cudaFuncSetAttribute(moe_fp16<FDIM, true>,
                         cudaFuncAttributeMaxDynamicSharedMemorySize, SMEM_BYTES);

    zero_kernel<<<(TOKENS * DDIM + 255) / 256, 256>>>(out, TOKENS * DDIM);
    gate_kernel<<<TOKENS, 256>>>(x, gw);

    dim3 g1(FDIM / BN, TOKENS / BM, NEXP);        // 32 x 32 x 8
    moe_fp16<DDIM, false><<<g1, NTH, SMEM_BYTES>>>(w1, b1, nullptr);

    dim3 g2((DDIM / BN) * 2, TOKENS / BM, NEXP);  // 16 x 32 x 8, k-split
    moe_fp16<FDIM, true><<<g2, NTH, SMEM_BYTES>>>(w2, b2, out);
}